// round 14
// baseline (speedup 1.0000x reference)
#include <cuda_runtime.h>
#include <math.h>

// Fused differentiable JPEG. One CTA = 128x16 pixel strip = 8 tiles of 16x16.
// R6: butterfly 8-point DCT/IDCT, .sat-folded clamps.
// R8: vectorized conflict-free shared accesses.
// R9/R11: 512 threads, one quad/thread in phases 1/3, 4 CTAs/SM.
// R13: transposes are intra-warp (8-thread groups) -> __syncwarp instead of
//      CTA barriers; phase 2 is one straight-line region (2 CTA barriers total).

__constant__ float cQTY[64] = {
  16,11,10,16,24,40,51,61,
  12,12,14,19,26,58,60,55,
  14,13,16,24,40,57,69,56,
  14,17,22,29,51,87,80,62,
  18,22,37,56,68,109,103,77,
  24,35,55,64,81,104,113,92,
  49,64,78,87,103,121,120,101,
  72,92,95,98,112,100,103,99};

__constant__ float cQTC[64] = {
  17,18,24,47,99,99,99,99,
  18,21,26,66,99,99,99,99,
  24,26,56,99,99,99,99,99,
  47,66,99,99,99,99,99,99,
  99,99,99,99,99,99,99,99,
  99,99,99,99,99,99,99,99,
  99,99,99,99,99,99,99,99,
  99,99,99,99,99,99,99,99};

#define C1 0.98078528040323044913f
#define C2 0.92387953251128675613f
#define C3 0.83146961230254523708f
#define C4 0.70710678118654752440f
#define C5 0.55557023301960222474f
#define C6 0.38268343236508977173f
#define C7 0.19509032201612826785f

__device__ __forceinline__ float poly_round_f(float x) {
  float r = rintf(x);               // round-half-to-even == jnp.round
  float d = x - r;
  return r + d * d * d;
}
__device__ __forceinline__ float poly_floor_f(float x) {
  return poly_round_f(x - 0.5f);
}
// Branchless diff_clip (identical to reference on all three regions).
__device__ __forceinline__ float diff_clip_f(float x, float lo, float hi) {
  float c = fminf(fmaxf(x, lo), hi);
  float d = x - c;
  float e = __expf(-fabsf(d));
  return fmaf(copysignf(0.02f, d), 1.0f - e, c);
}
__device__ __forceinline__ float diff_clip_exact(float x, float lo, float hi) {
  float out = x;
  if (x > hi) out = -0.02f * (expf(hi - x) - 1.0f) + hi;
  if (x < lo) out =  0.02f * (expf(x - lo) - 1.0f) + lo;
  return out;
}

// sat(h*0.5): exact fold of clip(x,-1,1) path
__device__ __forceinline__ float satmul_half(float h) {
  float y; asm("mul.rn.sat.f32 %0, %1, 0f3F000000;" : "=f"(y) : "f"(h)); return y;
}
// sat(v*(1/255)): folds output clip
__device__ __forceinline__ float sat_div255(float v) {
  float y; asm("mul.rn.sat.f32 %0, %1, 0f3B808081;" : "=f"(y) : "f"(v)); return y;
}

// 8-point DCT-II (unnormalized)
__device__ __forceinline__ void dct8(const float* x, float* T) {
  float e0 = x[0] + x[7], e1 = x[1] + x[6], e2 = x[2] + x[5], e3 = x[3] + x[4];
  float o0 = x[0] - x[7], o1 = x[1] - x[6], o2 = x[2] - x[5], o3 = x[3] - x[4];
  float a = e0 + e3, b = e1 + e2, f0 = e0 - e3, f1 = e1 - e2;
  T[0] = a + b;
  T[4] = C4 * (a - b);
  T[2] = fmaf(C2, f0,  C6 * f1);
  T[6] = fmaf(C6, f0, -C2 * f1);
  T[1] = fmaf(C1, o0, fmaf( C3, o1, fmaf( C5, o2,  C7 * o3)));
  T[3] = fmaf(C3, o0, fmaf(-C7, o1, fmaf(-C1, o2, -C5 * o3)));
  T[5] = fmaf(C5, o0, fmaf(-C1, o1, fmaf( C7, o2,  C3 * o3)));
  T[7] = fmaf(C7, o0, fmaf(-C5, o1, fmaf( C3, o2, -C1 * o3)));
}

// 8-point IDCT
__device__ __forceinline__ void idct8(const float* G, float* x) {
  float u  = fmaf( C4, G[4], G[0]);
  float w  = fmaf(-C4, G[4], G[0]);
  float p  = fmaf(C2, G[2],  C6 * G[6]);
  float qd = fmaf(C6, G[2], -C2 * G[6]);
  float E0 = u + p, E3 = u - p, E1 = w + qd, E2 = w - qd;
  float O0 = fmaf(C1, G[1], fmaf( C3, G[3], fmaf( C5, G[5],  C7 * G[7])));
  float O1 = fmaf(C3, G[1], fmaf(-C7, G[3], fmaf(-C1, G[5], -C5 * G[7])));
  float O2 = fmaf(C5, G[1], fmaf(-C1, G[3], fmaf( C7, G[5],  C3 * G[7])));
  float O3 = fmaf(C7, G[1], fmaf(-C5, G[3], fmaf( C3, G[5], -C1 * G[7])));
  x[0] = E0 + O0; x[7] = E0 - O0;
  x[1] = E1 + O1; x[6] = E1 - O1;
  x[2] = E2 + O2; x[5] = E2 - O2;
  x[3] = E3 + O3; x[4] = E3 - O3;
}

#define PITCH 132

__global__ __launch_bounds__(512, 4)
void jpeg_fused(const float* __restrict__ in, float* __restrict__ out) {
  const int  W     = 512;
  const long plane = 512L * 512L;

  const int t  = threadIdx.x;
  const int sx = blockIdx.x;
  const int ty = blockIdx.y;
  const int b  = blockIdx.z;

  __shared__ float yS [16 * PITCH];
  __shared__ float cbS[16 * PITCH];
  __shared__ float crS[16 * PITCH];
  __shared__ float tr [48 * 72];
  __shared__ float qtS[128];
  __shared__ float qrS[128];

  const float* inb  = in  + (long)b * 3 * plane + (long)(ty * 16) * W + sx * 128;
  float*       outb = out + (long)b * 3 * plane + (long)(ty * 16) * W + sx * 128;

  if (t < 128) {
    int c = t >> 6, e = t & 63;
    const float s = 99.875f;
    float base = c ? cQTC[e] : cQTY[e];
    float tq = poly_floor_f((base * s + 50.0f) / 100.0f);
    tq = diff_clip_exact(tq, 1.0f, 255.0f);
    qtS[t] = tq;
    qrS[t] = 1.0f / tq;
  }

  // ---- Phase 1: one quad per thread. load, clip+scale, RGB->YCbCr, stage ----
  {
    int row = t >> 5;
    int c4  = (t & 31) * 4;
    const float* p = inb + (long)row * W + c4;
    float4 R = *(const float4*)p;
    float4 G = *(const float4*)(p + plane);
    float4 B = *(const float4*)(p + 2 * plane);
    float4 Yv, Cbv, Crv;
    #define CONV(RX, GX, BX, YO, CBO, CRO)                                  \
    {                                                                       \
      float r  = satmul_half((RX) + 1.0f) * 255.0f;                         \
      float g  = satmul_half((GX) + 1.0f) * 255.0f;                         \
      float bl = satmul_half((BX) + 1.0f) * 255.0f;                         \
      YO  =  0.299f    * r + 0.587f    * g + 0.114f    * bl - 128.0f;       \
      CBO = -0.168736f * r - 0.331264f * g + 0.5f      * bl + 128.0f;       \
      CRO =  0.5f      * r - 0.418688f * g - 0.081312f * bl + 128.0f;       \
    }
    CONV(R.x, G.x, B.x, Yv.x, Cbv.x, Crv.x)
    CONV(R.y, G.y, B.y, Yv.y, Cbv.y, Crv.y)
    CONV(R.z, G.z, B.z, Yv.z, Cbv.z, Crv.z)
    CONV(R.w, G.w, B.w, Yv.w, Cbv.w, Crv.w)
    #undef CONV
    *(float4*)(yS  + row * PITCH + c4) = Yv;
    *(float4*)(cbS + row * PITCH + c4) = Cbv;
    *(float4*)(crS + row * PITCH + c4) = Crv;
  }
  __syncthreads();   // cross-warp: staged planes + quant tables ready

  // ---- Phase 2: straight-line per-warp pipeline (threads 0..383).
  //      Transposes exchange data only within 8-thread groups (same warp),
  //      so __syncwarp() is sufficient ordering. ----
  if (t < 384) {
    const int bk   = t >> 3;
    const int r    = t & 7;
    const int type = bk >> 3;
    const int tt   = bk & 7;
    float* trb = tr + bk * 72;

    int qrow = 0, col0 = 0;
    float X[8];
    if (type < 4) {
      qrow = (type >> 1) * 8 + r;
      col0 = tt * 16 + (type & 1) * 8;
      const float* yp = yS + qrow * PITCH + col0;
      float4 a = *(const float4*)yp;
      float4 c = *(const float4*)(yp + 4);
      X[0]=a.x; X[1]=a.y; X[2]=a.z; X[3]=a.w;
      X[4]=c.x; X[5]=c.y; X[6]=c.z; X[7]=c.w;
    } else {
      const float* src = (type == 4) ? cbS : crS;
      const float* r0p = src + (2 * r) * PITCH + tt * 16;
      const float* r1p = r0p + PITCH;
      float4 a0 = *(const float4*)(r0p);
      float4 a1 = *(const float4*)(r0p + 4);
      float4 a2 = *(const float4*)(r0p + 8);
      float4 a3 = *(const float4*)(r0p + 12);
      float4 b0 = *(const float4*)(r1p);
      float4 b1 = *(const float4*)(r1p + 4);
      float4 b2 = *(const float4*)(r1p + 8);
      float4 b3 = *(const float4*)(r1p + 12);
      X[0] = ((a0.x + a0.y) + (b0.x + b0.y)) * 0.25f - 128.0f;
      X[1] = ((a0.z + a0.w) + (b0.z + b0.w)) * 0.25f - 128.0f;
      X[2] = ((a1.x + a1.y) + (b1.x + b1.y)) * 0.25f - 128.0f;
      X[3] = ((a1.z + a1.w) + (b1.z + b1.w)) * 0.25f - 128.0f;
      X[4] = ((a2.x + a2.y) + (b2.x + b2.y)) * 0.25f - 128.0f;
      X[5] = ((a2.z + a2.w) + (b2.z + b2.w)) * 0.25f - 128.0f;
      X[6] = ((a3.x + a3.y) + (b3.x + b3.y)) * 0.25f - 128.0f;
      X[7] = ((a3.z + a3.w) + (b3.z + b3.w)) * 0.25f - 128.0f;
    }

    // Pass 1 (row DCT) -> transpose-1 (intra-warp)
    float T[8];
    dct8(X, T);
    #pragma unroll
    for (int v = 0; v < 8; v++) trb[r * 9 + v] = T[v];
    __syncwarp();
    float U[8];
    #pragma unroll
    for (int x = 0; x < 8; x++) U[x] = trb[x * 9 + r];

    // Pass 2 (col DCT) + quant/dequant
    float F8[8];
    dct8(U, F8);
    float q1 = ((r == 0) ? C4   : 1.0f) * 0.25f;
    float q0 = ((r == 0) ? 0.5f : C4)   * 0.25f;
    const int qoff = (type < 4) ? 0 : 64;
    float H[8];
    #pragma unroll
    for (int u = 0; u < 8; u++) {
      float su = (u == 0) ? q0 : q1;
      float F  = su * F8[u];
      float qv = qtS[qoff + u * 8 + r];
      float rq = qrS[qoff + u * 8 + r];
      float c  = poly_round_f(F * rq);
      H[u] = su * (c * qv);
    }

    // Pass 3 (col IDCT) -> transpose-2 (intra-warp)
    float Gv[8];
    idct8(H, Gv);
    __syncwarp();           // all reads of transpose-1 done before overwrite
    #pragma unroll
    for (int x = 0; x < 8; x++) trb[x * 9 + r] = Gv[x];
    __syncwarp();
    float P[8];
    #pragma unroll
    for (int v = 0; v < 8; v++) P[v] = trb[r * 9 + v];

    // Pass 4 (row IDCT) + 128, write decoded planes
    float pix[8];
    idct8(P, pix);
    #pragma unroll
    for (int y = 0; y < 8; y++) pix[y] += 128.0f;

    if (type < 4) {
      float* yp = yS + qrow * PITCH + col0;
      *(float4*)yp       = make_float4(pix[0], pix[1], pix[2], pix[3]);
      *(float4*)(yp + 4) = make_float4(pix[4], pix[5], pix[6], pix[7]);
    } else {
      float* cp = ((type == 4) ? cbS : crS) + r * PITCH + tt * 8;
      *(float4*)cp       = make_float4(pix[0], pix[1], pix[2], pix[3]);
      *(float4*)(cp + 4) = make_float4(pix[4], pix[5], pix[6], pix[7]);
    }
  }
  __syncthreads();   // cross-warp: decoded planes ready

  // ---- Phase 3: one quad per thread. 1 LDS.128 + 2 LDS.64, assemble, store ----
  {
    int row = t >> 5;
    int c4  = (t & 31) * 4;
    float4 Yv = *(const float4*)(yS + row * PITCH + c4);
    int cc0 = (c4 >> 4) * 8 + ((c4 & 15) >> 1);       // even -> float2 aligned
    float2 cb2 = *(const float2*)(cbS + (row >> 1) * PITCH + cc0);
    float2 cr2 = *(const float2*)(crS + (row >> 1) * PITCH + cc0);
    float rr[4], gg[4], bb[4];
    float Ys[4] = {Yv.x, Yv.y, Yv.z, Yv.w};
    #pragma unroll
    for (int l = 0; l < 4; l++) {
      float cbv = ((l < 2) ? cb2.x : cb2.y) - 128.0f;
      float crv = ((l < 2) ? cr2.x : cr2.y) - 128.0f;
      float Y  = Ys[l];
      float R  = Y + 1.402f    * crv;
      float G  = Y - 0.344136f * cbv - 0.714136f * crv;
      float B  = Y + 1.772f    * cbv;
      R = diff_clip_f(R, 0.0f, 255.0f);
      G = diff_clip_f(G, 0.0f, 255.0f);
      B = diff_clip_f(B, 0.0f, 255.0f);
      rr[l] = fmaf(sat_div255(R), 2.0f, -1.0f);
      gg[l] = fmaf(sat_div255(G), 2.0f, -1.0f);
      bb[l] = fmaf(sat_div255(B), 2.0f, -1.0f);
    }
    float* p = outb + (long)row * W + c4;
    *(float4*)p               = make_float4(rr[0], rr[1], rr[2], rr[3]);
    *(float4*)(p + plane)     = make_float4(gg[0], gg[1], gg[2], gg[3]);
    *(float4*)(p + 2 * plane) = make_float4(bb[0], bb[1], bb[2], bb[3]);
  }
}

extern "C" void kernel_launch(void* const* d_in, const int* in_sizes, int n_in,
                              void* d_out, int out_size) {
  const float* in = (const float*)d_in[0];
  float* out = (float*)d_out;
  int B = in_sizes[0] / (3 * 512 * 512);
  dim3 grid(4, 32, B);
  jpeg_fused<<<grid, 512>>>(in, out);
}

// round 15
// speedup vs baseline: 1.1798x; 1.1798x over previous
#include <cuda_runtime.h>
#include <math.h>

// Fused differentiable JPEG. One CTA = 128x16 pixel strip = 8 tiles of 16x16.
// R6: butterfly 8-point DCT/IDCT, .sat-folded clamps.
// R8: vectorized conflict-free shared accesses.
// R9/R11: 512 threads, one quad/thread in phases 1/3, 4 CTAs/SM.
// R14: phase-3 diff_clip eliminated -- the final clip(-1,1) makes the 0.02*exp
//      soft region exactly equivalent to a hard clamp, so sat(x/255) alone
//      reproduces the reference. Kills 3 MUFU.EX2/pixel (the saturated pipe).

__constant__ float cQTY[64] = {
  16,11,10,16,24,40,51,61,
  12,12,14,19,26,58,60,55,
  14,13,16,24,40,57,69,56,
  14,17,22,29,51,87,80,62,
  18,22,37,56,68,109,103,77,
  24,35,55,64,81,104,113,92,
  49,64,78,87,103,121,120,101,
  72,92,95,98,112,100,103,99};

__constant__ float cQTC[64] = {
  17,18,24,47,99,99,99,99,
  18,21,26,66,99,99,99,99,
  24,26,56,99,99,99,99,99,
  47,66,99,99,99,99,99,99,
  99,99,99,99,99,99,99,99,
  99,99,99,99,99,99,99,99,
  99,99,99,99,99,99,99,99,
  99,99,99,99,99,99,99,99};

#define C1 0.98078528040323044913f
#define C2 0.92387953251128675613f
#define C3 0.83146961230254523708f
#define C4 0.70710678118654752440f
#define C5 0.55557023301960222474f
#define C6 0.38268343236508977173f
#define C7 0.19509032201612826785f

__device__ __forceinline__ float poly_round_f(float x) {
  float r = rintf(x);               // round-half-to-even == jnp.round
  float d = x - r;
  return r + d * d * d;
}
__device__ __forceinline__ float poly_floor_f(float x) {
  return poly_round_f(x - 0.5f);
}
// Exact diff_clip for the quant-table setup (runs once, 128 threads).
__device__ __forceinline__ float diff_clip_exact(float x, float lo, float hi) {
  float out = x;
  if (x > hi) out = -0.02f * (expf(hi - x) - 1.0f) + hi;
  if (x < lo) out =  0.02f * (expf(x - lo) - 1.0f) + lo;
  return out;
}

// sat(h*0.5): exact fold of clip(x,-1,1) path
__device__ __forceinline__ float satmul_half(float h) {
  float y; asm("mul.rn.sat.f32 %0, %1, 0f3F000000;" : "=f"(y) : "f"(h)); return y;
}
// sat(v*(1/255)): folds diff_clip(0,255) + *2/255-1 + clip(-1,1) (see header note)
__device__ __forceinline__ float sat_div255(float v) {
  float y; asm("mul.rn.sat.f32 %0, %1, 0f3B808081;" : "=f"(y) : "f"(v)); return y;
}

// 8-point DCT-II (unnormalized)
__device__ __forceinline__ void dct8(const float* x, float* T) {
  float e0 = x[0] + x[7], e1 = x[1] + x[6], e2 = x[2] + x[5], e3 = x[3] + x[4];
  float o0 = x[0] - x[7], o1 = x[1] - x[6], o2 = x[2] - x[5], o3 = x[3] - x[4];
  float a = e0 + e3, b = e1 + e2, f0 = e0 - e3, f1 = e1 - e2;
  T[0] = a + b;
  T[4] = C4 * (a - b);
  T[2] = fmaf(C2, f0,  C6 * f1);
  T[6] = fmaf(C6, f0, -C2 * f1);
  T[1] = fmaf(C1, o0, fmaf( C3, o1, fmaf( C5, o2,  C7 * o3)));
  T[3] = fmaf(C3, o0, fmaf(-C7, o1, fmaf(-C1, o2, -C5 * o3)));
  T[5] = fmaf(C5, o0, fmaf(-C1, o1, fmaf( C7, o2,  C3 * o3)));
  T[7] = fmaf(C7, o0, fmaf(-C5, o1, fmaf( C3, o2, -C1 * o3)));
}

// 8-point IDCT
__device__ __forceinline__ void idct8(const float* G, float* x) {
  float u  = fmaf( C4, G[4], G[0]);
  float w  = fmaf(-C4, G[4], G[0]);
  float p  = fmaf(C2, G[2],  C6 * G[6]);
  float qd = fmaf(C6, G[2], -C2 * G[6]);
  float E0 = u + p, E3 = u - p, E1 = w + qd, E2 = w - qd;
  float O0 = fmaf(C1, G[1], fmaf( C3, G[3], fmaf( C5, G[5],  C7 * G[7])));
  float O1 = fmaf(C3, G[1], fmaf(-C7, G[3], fmaf(-C1, G[5], -C5 * G[7])));
  float O2 = fmaf(C5, G[1], fmaf(-C1, G[3], fmaf( C7, G[5],  C3 * G[7])));
  float O3 = fmaf(C7, G[1], fmaf(-C5, G[3], fmaf( C3, G[5], -C1 * G[7])));
  x[0] = E0 + O0; x[7] = E0 - O0;
  x[1] = E1 + O1; x[6] = E1 - O1;
  x[2] = E2 + O2; x[5] = E2 - O2;
  x[3] = E3 + O3; x[4] = E3 - O3;
}

#define PITCH 132

__global__ __launch_bounds__(512, 4)
void jpeg_fused(const float* __restrict__ in, float* __restrict__ out) {
  const int  W     = 512;
  const long plane = 512L * 512L;

  const int t  = threadIdx.x;
  const int sx = blockIdx.x;
  const int ty = blockIdx.y;
  const int b  = blockIdx.z;

  __shared__ float yS [16 * PITCH];
  __shared__ float cbS[16 * PITCH];
  __shared__ float crS[16 * PITCH];
  __shared__ float tr [48 * 72];
  __shared__ float qtS[128];
  __shared__ float qrS[128];

  const float* inb  = in  + (long)b * 3 * plane + (long)(ty * 16) * W + sx * 128;
  float*       outb = out + (long)b * 3 * plane + (long)(ty * 16) * W + sx * 128;

  if (t < 128) {
    int c = t >> 6, e = t & 63;
    const float s = 99.875f;
    float base = c ? cQTC[e] : cQTY[e];
    float tq = poly_floor_f((base * s + 50.0f) / 100.0f);
    tq = diff_clip_exact(tq, 1.0f, 255.0f);
    qtS[t] = tq;
    qrS[t] = 1.0f / tq;
  }

  // ---- Phase 1: one quad per thread. load, clip+scale, RGB->YCbCr, stage ----
  {
    int row = t >> 5;
    int c4  = (t & 31) * 4;
    const float* p = inb + (long)row * W + c4;
    float4 R = *(const float4*)p;
    float4 G = *(const float4*)(p + plane);
    float4 B = *(const float4*)(p + 2 * plane);
    float4 Yv, Cbv, Crv;
    #define CONV(RX, GX, BX, YO, CBO, CRO)                                  \
    {                                                                       \
      float r  = satmul_half((RX) + 1.0f) * 255.0f;                         \
      float g  = satmul_half((GX) + 1.0f) * 255.0f;                         \
      float bl = satmul_half((BX) + 1.0f) * 255.0f;                         \
      YO  =  0.299f    * r + 0.587f    * g + 0.114f    * bl - 128.0f;       \
      CBO = -0.168736f * r - 0.331264f * g + 0.5f      * bl + 128.0f;       \
      CRO =  0.5f      * r - 0.418688f * g - 0.081312f * bl + 128.0f;       \
    }
    CONV(R.x, G.x, B.x, Yv.x, Cbv.x, Crv.x)
    CONV(R.y, G.y, B.y, Yv.y, Cbv.y, Crv.y)
    CONV(R.z, G.z, B.z, Yv.z, Cbv.z, Crv.z)
    CONV(R.w, G.w, B.w, Yv.w, Cbv.w, Crv.w)
    #undef CONV
    *(float4*)(yS  + row * PITCH + c4) = Yv;
    *(float4*)(cbS + row * PITCH + c4) = Cbv;
    *(float4*)(crS + row * PITCH + c4) = Crv;
  }
  __syncthreads();

  // ---- Phase 2: per-thread block-row pipeline (threads 0..383) ----
  const int  bk     = t >> 3;
  const int  r      = t & 7;
  const int  type   = bk >> 3;       // valid when t < 384
  const int  tt     = bk & 7;
  const bool active = (t < 384);
  float* trb = tr + bk * 72;

  int qrow = 0, col0 = 0;

  if (active) {
    float X[8];
    if (type < 4) {
      qrow = (type >> 1) * 8 + r;
      col0 = tt * 16 + (type & 1) * 8;
      const float* yp = yS + qrow * PITCH + col0;
      float4 a = *(const float4*)yp;
      float4 c = *(const float4*)(yp + 4);
      X[0]=a.x; X[1]=a.y; X[2]=a.z; X[3]=a.w;
      X[4]=c.x; X[5]=c.y; X[6]=c.z; X[7]=c.w;
    } else {
      const float* src = (type == 4) ? cbS : crS;
      const float* r0p = src + (2 * r) * PITCH + tt * 16;
      const float* r1p = r0p + PITCH;
      float4 a0 = *(const float4*)(r0p);
      float4 a1 = *(const float4*)(r0p + 4);
      float4 a2 = *(const float4*)(r0p + 8);
      float4 a3 = *(const float4*)(r0p + 12);
      float4 b0 = *(const float4*)(r1p);
      float4 b1 = *(const float4*)(r1p + 4);
      float4 b2 = *(const float4*)(r1p + 8);
      float4 b3 = *(const float4*)(r1p + 12);
      X[0] = ((a0.x + a0.y) + (b0.x + b0.y)) * 0.25f - 128.0f;
      X[1] = ((a0.z + a0.w) + (b0.z + b0.w)) * 0.25f - 128.0f;
      X[2] = ((a1.x + a1.y) + (b1.x + b1.y)) * 0.25f - 128.0f;
      X[3] = ((a1.z + a1.w) + (b1.z + b1.w)) * 0.25f - 128.0f;
      X[4] = ((a2.x + a2.y) + (b2.x + b2.y)) * 0.25f - 128.0f;
      X[5] = ((a2.z + a2.w) + (b2.z + b2.w)) * 0.25f - 128.0f;
      X[6] = ((a3.x + a3.y) + (b3.x + b3.y)) * 0.25f - 128.0f;
      X[7] = ((a3.z + a3.w) + (b3.z + b3.w)) * 0.25f - 128.0f;
    }
    // Pass 1 (row DCT) -> transpose-1 store
    float T[8];
    dct8(X, T);
    #pragma unroll
    for (int v = 0; v < 8; v++) trb[r * 9 + v] = T[v];
  }
  __syncthreads();

  if (active) {
    // transpose-1 load (column r) -> pass 2 (col DCT) + quant/dequant
    float U[8];
    #pragma unroll
    for (int x = 0; x < 8; x++) U[x] = trb[x * 9 + r];
    float F8[8];
    dct8(U, F8);
    float q1 = ((r == 0) ? C4   : 1.0f) * 0.25f;
    float q0 = ((r == 0) ? 0.5f : C4)   * 0.25f;
    const int qoff = (type < 4) ? 0 : 64;
    float H[8];
    #pragma unroll
    for (int u = 0; u < 8; u++) {
      float su = (u == 0) ? q0 : q1;
      float F  = su * F8[u];
      float qv = qtS[qoff + u * 8 + r];
      float rq = qrS[qoff + u * 8 + r];
      float c  = poly_round_f(F * rq);
      H[u] = su * (c * qv);
    }
    // Pass 3 (col IDCT) -> transpose-2 store (column r)
    float Gv[8];
    idct8(H, Gv);
    #pragma unroll
    for (int x = 0; x < 8; x++) trb[x * 9 + r] = Gv[x];
  }
  __syncthreads();

  if (active) {
    // transpose-2 load (row r) -> pass 4 (row IDCT) + 128, write planes
    float P[8];
    #pragma unroll
    for (int v = 0; v < 8; v++) P[v] = trb[r * 9 + v];
    float pix[8];
    idct8(P, pix);
    #pragma unroll
    for (int y = 0; y < 8; y++) pix[y] += 128.0f;

    if (type < 4) {
      float* yp = yS + qrow * PITCH + col0;
      *(float4*)yp       = make_float4(pix[0], pix[1], pix[2], pix[3]);
      *(float4*)(yp + 4) = make_float4(pix[4], pix[5], pix[6], pix[7]);
    } else {
      float* cp = ((type == 4) ? cbS : crS) + r * PITCH + tt * 8;
      *(float4*)cp       = make_float4(pix[0], pix[1], pix[2], pix[3]);
      *(float4*)(cp + 4) = make_float4(pix[4], pix[5], pix[6], pix[7]);
    }
  }
  __syncthreads();

  // ---- Phase 3: one quad per thread. Assemble RGB; the final
  //      clip(-1,1) makes diff_clip(0,255) equivalent to a hard clamp,
  //      so sat(x/255)*2-1 is the exact reference result. ----
  {
    int row = t >> 5;
    int c4  = (t & 31) * 4;
    float4 Yv = *(const float4*)(yS + row * PITCH + c4);
    int cc0 = (c4 >> 4) * 8 + ((c4 & 15) >> 1);       // even -> float2 aligned
    float2 cb2 = *(const float2*)(cbS + (row >> 1) * PITCH + cc0);
    float2 cr2 = *(const float2*)(crS + (row >> 1) * PITCH + cc0);
    float rr[4], gg[4], bb[4];
    float Ys[4] = {Yv.x, Yv.y, Yv.z, Yv.w};
    #pragma unroll
    for (int l = 0; l < 4; l++) {
      float cbv = ((l < 2) ? cb2.x : cb2.y) - 128.0f;
      float crv = ((l < 2) ? cr2.x : cr2.y) - 128.0f;
      float Y  = Ys[l];
      float R  = Y + 1.402f    * crv;
      float G  = Y - 0.344136f * cbv - 0.714136f * crv;
      float B  = Y + 1.772f    * cbv;
      rr[l] = fmaf(sat_div255(R), 2.0f, -1.0f);
      gg[l] = fmaf(sat_div255(G), 2.0f, -1.0f);
      bb[l] = fmaf(sat_div255(B), 2.0f, -1.0f);
    }
    float* p = outb + (long)row * W + c4;
    *(float4*)p               = make_float4(rr[0], rr[1], rr[2], rr[3]);
    *(float4*)(p + plane)     = make_float4(gg[0], gg[1], gg[2], gg[3]);
    *(float4*)(p + 2 * plane) = make_float4(bb[0], bb[1], bb[2], bb[3]);
  }
}

extern "C" void kernel_launch(void* const* d_in, const int* in_sizes, int n_in,
                              void* d_out, int out_size) {
  const float* in = (const float*)d_in[0];
  float* out = (float*)d_out;
  int B = in_sizes[0] / (3 * 512 * 512);
  dim3 grid(4, 32, B);
  jpeg_fused<<<grid, 512>>>(in, out);
}